// round 14
// baseline (speedup 1.0000x reference)
#include <cuda_runtime.h>
#include <cuda_fp16.h>
#include <cstddef>

#define NN   100000
#define EE   1600000
#define GG   100
#define NPG  1000
#define EPG  16000
#define HH   128
#define FIN  64
#define RD   64
#define SLOPE 0.01f
#define EPSN  1e-5f

typedef unsigned long long u64;
typedef unsigned int u32;

__device__ __forceinline__ u64 pack2(float a, float b) {
    u64 r; asm("mov.b64 %0,{%1,%2};" : "=l"(r) : "f"(a), "f"(b)); return r;
}
__device__ __forceinline__ u64 ffma2(u64 a, u64 b, u64 c) {
    u64 d; asm("fma.rn.f32x2 %0,%1,%2,%3;" : "=l"(d) : "l"(a), "l"(b), "l"(c)); return d;
}
__device__ __forceinline__ float2 unpack2(u64 v) {
    float2 f; asm("mov.b64 {%0,%1},%2;" : "=f"(f.x), "=f"(f.y) : "l"(v)); return f;
}
__device__ __forceinline__ float leaky(float x) { return x >= 0.f ? x : SLOPE * x; }

// ---------------- scratch ----------------
__device__ int    d_rowstart[NN + 1];
__device__ int2   d_edge[EE];              // (src, __float_as_int(w))
__device__ float  d_outis[NN];
__device__ float  d_inis[NN];
__device__ __half d_hpre16[(size_t)NN * HH];
__device__ __half d_conv16[(size_t)NN * HH];
__device__ __half d_hpost16[(size_t)NN * HH];
__device__ float  d_pool1[GG * HH];
__device__ float  d_m1[GG * HH];
__device__ float  d_pool2[GG * HH];
__device__ float  d_m2[GG * HH];
__device__ float  d_S1a[GG * HH];
__device__ float  d_S2a[GG * HH];
__device__ float  d_S1b[GG * HH];
__device__ float  d_S2b[GG * HH];

// ---------------- fused per-graph CSR build + accumulator zeroing ----------------
__global__ __launch_bounds__(512)
void csr_kernel(const int* __restrict__ src, const int* __restrict__ dst,
                const float* __restrict__ ew) {
    __shared__ int cin[NPG], cout[NPG], cur[NPG], part[256];
    int g = blockIdx.x, t = threadIdx.x;
    int nbase = g * NPG;
    int e0 = g * EPG;

    if (t < 128) {
        int i = g * HH + t;
        d_pool1[i] = 0.f; d_pool2[i] = 0.f;
        d_m1[i] = 0.f;    d_m2[i] = 0.f;
        d_S1a[i] = 0.f;   d_S2a[i] = 0.f;
        d_S1b[i] = 0.f;   d_S2b[i] = 0.f;
    }
    for (int i = t; i < NPG; i += 512) { cin[i] = 0; cout[i] = 0; }
    __syncthreads();

    for (int e = t; e < EPG; e += 512) {
        atomicAdd(&cin[dst[e0 + e] - nbase], 1);
        atomicAdd(&cout[src[e0 + e] - nbase], 1);
    }
    __syncthreads();

    for (int i = t; i < NPG; i += 512) {
        int ci = cin[i];  if (ci < 1) ci = 1;
        int co = cout[i]; if (co < 1) co = 1;
        d_inis[nbase + i]  = rsqrtf((float)ci);
        d_outis[nbase + i] = rsqrtf((float)co);
    }

    int s = 0;
    if (t < 250) {
#pragma unroll
        for (int j = 0; j < 4; j++) s += cin[t * 4 + j];
    }
    if (t < 256) part[t] = s;
    __syncthreads();
    for (int o = 1; o < 256; o <<= 1) {
        int v = 0;
        if (t >= o && t < 256) v = part[t - o];
        __syncthreads();
        if (t < 256) part[t] += v;
        __syncthreads();
    }
    int run = (t == 0 || t >= 256) ? 0 : part[t - 1];
    if (t < 250) {
#pragma unroll
        for (int j = 0; j < 4; j++) {
            int i = t * 4 + j;
            int c = cin[i];
            cur[i] = run;
            d_rowstart[nbase + i] = e0 + run;
            run += c;
        }
    }
    if (g == 0 && t == 511) d_rowstart[NN] = EE;
    __syncthreads();

    for (int e = t; e < EPG; e += 512) {
        int sv = src[e0 + e];
        int d  = dst[e0 + e] - nbase;
        float wv = ew[e0 + e];
        int p = atomicAdd(&cur[d], 1);
        d_edge[e0 + p] = make_int2(sv, __float_as_int(wv));
    }
}

// ---------------- tiled GEMM, f32x2, CTA=128x128, thread=8x8 ----------------
// POOL=false: Y[r] = (RS? scale[r]:1) * X[r] @ W  -> fp16
// POOL=true : pool[g] += sum_r leaky(X[r]@W + bias)
// IN16: X is fp16 (converted during staging)
template <int K, bool RS, bool POOL, bool IN16>
__global__ __launch_bounds__(256)
void gemm_kernel(const void* __restrict__ Xv,
                 const float* __restrict__ W,          // K x 128 row-major
                 const float* __restrict__ rowscale,
                 const float* __restrict__ bias,
                 __half* __restrict__ Y,
                 float* __restrict__ pool) {
    __shared__ float Xs[32][128];
    __shared__ float Ws[32][128];
    __shared__ float psum[128];
    __shared__ float bsm[128];
    int tid = threadIdx.x;
    int tx = tid & 15;
    int ty = tid >> 4;

    int row0, g = 0, validrows = 128;
    if (POOL) {
        g = blockIdx.x >> 3;
        int chunk = blockIdx.x & 7;
        row0 = g * NPG + chunk * 128;
        validrows = NPG - chunk * 128; if (validrows > 128) validrows = 128;
        if (tid < 128) { psum[tid] = 0.f; bsm[tid] = bias[tid]; }
    } else {
        row0 = blockIdx.x * 128;
    }

    u64 acc[32];
#pragma unroll
    for (int i = 0; i < 32; i++) acc[i] = 0ull;

    for (int k0 = 0; k0 < K; k0 += 32) {
        __syncthreads();
#pragma unroll
        for (int i = 0; i < 4; i++) {
            int s = tid + i * 256;
            int row = s >> 3;
            int kq = s & 7;
            int grow = row0 + row;
            float4 v = make_float4(0.f, 0.f, 0.f, 0.f);
            if (grow < NN) {
                if (IN16) {
                    uint2 raw = *(const uint2*)((const __half*)Xv + (size_t)grow * K + k0 + kq * 4);
                    float2 a = __half22float2(*(__half2*)&raw.x);
                    float2 b = __half22float2(*(__half2*)&raw.y);
                    v = make_float4(a.x, a.y, b.x, b.y);
                } else {
                    v = *(const float4*)((const float*)Xv + (size_t)grow * K + k0 + kq * 4);
                }
                if (RS) {
                    float sc = rowscale[grow];
                    v.x *= sc; v.y *= sc; v.z *= sc; v.w *= sc;
                }
            }
            Xs[kq * 4 + 0][row] = v.x;
            Xs[kq * 4 + 1][row] = v.y;
            Xs[kq * 4 + 2][row] = v.z;
            Xs[kq * 4 + 3][row] = v.w;
        }
#pragma unroll
        for (int i = 0; i < 4; i++) {
            int s = tid + i * 256;
            int k = s >> 5;
            int cq = s & 31;
            *(float4*)&Ws[k][cq * 4] =
                *(const float4*)(W + (size_t)(k0 + k) * 128 + cq * 4);
        }
        __syncthreads();

#pragma unroll 8
        for (int kk = 0; kk < 32; kk++) {
            float xr[8];
            *(float4*)&xr[0] = *(const float4*)&Xs[kk][ty * 8];
            *(float4*)&xr[4] = *(const float4*)&Xs[kk][ty * 8 + 4];
            u64 x2[8];
#pragma unroll
            for (int r = 0; r < 8; r++) x2[r] = pack2(xr[r], xr[r]);
            const double2* wp = (const double2*)&Ws[kk][tx * 8];
            double2 wa = wp[0], wb = wp[1];
            u64 w2[4];
            w2[0] = __double_as_longlong(wa.x);
            w2[1] = __double_as_longlong(wa.y);
            w2[2] = __double_as_longlong(wb.x);
            w2[3] = __double_as_longlong(wb.y);
#pragma unroll
            for (int r = 0; r < 8; r++) {
#pragma unroll
                for (int c = 0; c < 4; c++)
                    acc[r * 4 + c] = ffma2(x2[r], w2[c], acc[r * 4 + c]);
            }
        }
    }

    if (!POOL) {
#pragma unroll
        for (int rr = 0; rr < 8; rr++) {
            int grow = row0 + ty * 8 + rr;
            if (grow < NN) {
                float2 p0 = unpack2(acc[rr * 4 + 0]);
                float2 p1 = unpack2(acc[rr * 4 + 1]);
                float2 p2 = unpack2(acc[rr * 4 + 2]);
                float2 p3 = unpack2(acc[rr * 4 + 3]);
                __half2 h0 = __floats2half2_rn(p0.x, p0.y);
                __half2 h1 = __floats2half2_rn(p1.x, p1.y);
                __half2 h2 = __floats2half2_rn(p2.x, p2.y);
                __half2 h3 = __floats2half2_rn(p3.x, p3.y);
                uint4 u;
                u.x = *(u32*)&h0; u.y = *(u32*)&h1;
                u.z = *(u32*)&h2; u.w = *(u32*)&h3;
                *(uint4*)(Y + (size_t)grow * 128 + tx * 8) = u;
            }
        }
    } else {
        float b[8];
#pragma unroll
        for (int j = 0; j < 8; j++) b[j] = bsm[tx * 8 + j];
        float cs[8];
#pragma unroll
        for (int j = 0; j < 8; j++) cs[j] = 0.f;
#pragma unroll
        for (int rr = 0; rr < 8; rr++) {
            if (ty * 8 + rr < validrows) {
#pragma unroll
                for (int c = 0; c < 4; c++) {
                    float2 p = unpack2(acc[rr * 4 + c]);
                    cs[2 * c]     += leaky(p.x + b[2 * c]);
                    cs[2 * c + 1] += leaky(p.y + b[2 * c + 1]);
                }
            }
        }
#pragma unroll
        for (int j = 0; j < 8; j++) atomicAdd(&psum[tx * 8 + j], cs[j]);
        __syncthreads();
        if (tid < 128) atomicAdd(&pool[g * 128 + tid], psum[tid]);
    }
}

// ---------------- edge aggregation + fused GraphNorm stats ----------------
// warp/node; 8 nodes per CTA; 8 | 1000 so a CTA never straddles a graph.
__global__ __launch_bounds__(256)
void conv_kernel(const __half* __restrict__ hpre, __half* __restrict__ out,
                 float* __restrict__ S1, float* __restrict__ S2) {
    __shared__ float sS1[128], sS2[128];
    int tid = threadIdx.x;
    int gt = blockIdx.x * 256 + tid;
    int node = gt >> 5;
    int lane = gt & 31;
    if (tid < 128) { sS1[tid] = 0.f; sS2[tid] = 0.f; }
    __syncthreads();

    if (node < NN) {
        int e0 = d_rowstart[node];
        int e1 = d_rowstart[node + 1];
        const uint2* hp = (const uint2*)hpre;
        float4 acc = make_float4(0.f, 0.f, 0.f, 0.f);
        for (int base = e0; base < e1; base += 32) {
            int m = e1 - base; if (m > 32) m = 32;
            int sv = 0; float wv = 0.f;
            if (lane < m) {
                int2 p = d_edge[base + lane];
                sv = p.x;
                wv = __int_as_float(p.y);
            }
            for (int j = 0; j < m; j++) {
                int s   = __shfl_sync(0xFFFFFFFFu, sv, j);
                float w = __shfl_sync(0xFFFFFFFFu, wv, j);
                uint2 v = hp[(size_t)s * 32 + lane];
                float2 fa = __half22float2(*(__half2*)&v.x);
                float2 fb = __half22float2(*(__half2*)&v.y);
                acc.x += fa.x * w; acc.y += fa.y * w;
                acc.z += fb.x * w; acc.w += fb.y * w;
            }
        }
        float sc = d_inis[node];
        __half2 h0 = __floats2half2_rn(acc.x * sc, acc.y * sc);
        __half2 h1 = __floats2half2_rn(acc.z * sc, acc.w * sc);
        uint2 u; u.x = *(u32*)&h0; u.y = *(u32*)&h1;
        ((uint2*)out)[(size_t)node * 32 + lane] = u;

        // stats on the rounded values normB will read
        float2 r0 = __half22float2(h0);
        float2 r1 = __half22float2(h1);
        int f = lane * 4;
        atomicAdd(&sS1[f + 0], r0.x); atomicAdd(&sS2[f + 0], r0.x * r0.x);
        atomicAdd(&sS1[f + 1], r0.y); atomicAdd(&sS2[f + 1], r0.y * r0.y);
        atomicAdd(&sS1[f + 2], r1.x); atomicAdd(&sS2[f + 2], r1.x * r1.x);
        atomicAdd(&sS1[f + 3], r1.y); atomicAdd(&sS2[f + 3], r1.y * r1.y);
    }
    __syncthreads();
    if (tid < 128) {
        int g = (blockIdx.x * 8) / NPG;   // CTA's 8 nodes share one graph
        atomicAdd(&S1[g * HH + tid], sS1[tid]);
        atomicAdd(&S2[g * HH + tid], sS2[tid]);
    }
}

// ---------------- GraphNorm apply + leaky + fused m-pool (fp16 in/out) ----------------
__global__ __launch_bounds__(256)
void normB_kernel(const __half* __restrict__ Yin,
                  const float* __restrict__ S1, const float* __restrict__ S2,
                  const float* __restrict__ alpha, const float* __restrict__ gamma_,
                  const float* __restrict__ beta, __half* __restrict__ Yout,
                  float* __restrict__ mout) {
    int g = blockIdx.x >> 2;
    int q = blockIdx.x & 3;
    int f = threadIdx.x & 127;
    int half = threadIdx.x >> 7;
    float a = alpha[f], gm = gamma_[f], bt = beta[f];
    float mean = S1[g * HH + f] * (1.f / NPG);
    float var = S2[g * HH + f] * (1.f / NPG) - (2.f * a - a * a) * mean * mean;
    float inv = rsqrtf(var + EPSN);
    float am = a * mean;
    size_t off = ((size_t)g * NPG + q * 250 + half * 125) * HH + f;
    const __half* base = Yin + off;
    __half* obase = Yout + off;
    float so = 0.f;
#pragma unroll 5
    for (int i = 0; i < 125; i++) {
        float v = __half2float(base[(size_t)i * HH]);
        float o = leaky(gm * (v - am) * inv + bt);
        obase[(size_t)i * HH] = __float2half(o);
        so += o;
    }
    __shared__ float sm[256];
    sm[threadIdx.x] = so;
    __syncthreads();
    if (half == 0) atomicAdd(&mout[g * HH + f], sm[f] + sm[128 + f]);
}

// ---------------- final readout assembly ----------------
__global__ __launch_bounds__(128)
void final_kernel(const float* __restrict__ p1, const float* __restrict__ m1,
                  const float* __restrict__ p2, const float* __restrict__ m2,
                  const float* __restrict__ r1w2, const float* __restrict__ r1b2,
                  const float* __restrict__ r2w2, const float* __restrict__ r2b2,
                  float* __restrict__ out) {
    int g = blockIdx.x;
    int t = threadIdx.x;
    const float inv = 1.f / NPG;
    if (t < RD) {
        float a1 = 0.f, a2 = 0.f;
        const float* pp1 = p1 + g * HH;
        const float* pp2 = p2 + g * HH;
#pragma unroll 4
        for (int f = 0; f < HH; f++) {
            a1 += pp1[f] * r1w2[f * RD + t];
            a2 += pp2[f] * r2w2[f * RD + t];
        }
        a1 = a1 * inv + r1b2[t];
        a2 = a2 * inv + r2b2[t];
        out[g * 384 + t]       = leaky(leaky(a1));
        out[g * 384 + 192 + t] = leaky(leaky(a2));
    }
    out[g * 384 + 64 + t]  = leaky(m1[g * HH + t] * inv);
    out[g * 384 + 256 + t] = leaky(m2[g * HH + t] * inv);
}

// ---------------- host launch ----------------
extern "C" void kernel_launch(void* const* d_in, const int* in_sizes, int n_in,
                              void* d_out, int out_size) {
    const float* node_feats = (const float*)d_in[0];
    const float* ew         = (const float*)d_in[1];
    const float* W1         = (const float*)d_in[2];
    const float* W2         = (const float*)d_in[3];
    const float* gn1a       = (const float*)d_in[4];
    const float* gn1g       = (const float*)d_in[5];
    const float* gn1b       = (const float*)d_in[6];
    const float* gn2a       = (const float*)d_in[7];
    const float* gn2g       = (const float*)d_in[8];
    const float* gn2b       = (const float*)d_in[9];
    const float* r1w1       = (const float*)d_in[10];
    const float* r1b1       = (const float*)d_in[11];
    const float* r1w2       = (const float*)d_in[12];
    const float* r1b2       = (const float*)d_in[13];
    const float* r2w1       = (const float*)d_in[14];
    const float* r2b1       = (const float*)d_in[15];
    const float* r2w2       = (const float*)d_in[16];
    const float* r2b2       = (const float*)d_in[17];
    const int*   src        = (const int*)d_in[18];
    const int*   dst        = (const int*)d_in[19];
    float* out = (float*)d_out;

    void *hpre16, *conv16, *hpost16, *pool1, *m1, *pool2, *m2, *outis;
    void *s1a, *s2a, *s1b, *s2b;
    cudaGetSymbolAddress(&hpre16,  d_hpre16);
    cudaGetSymbolAddress(&conv16,  d_conv16);
    cudaGetSymbolAddress(&hpost16, d_hpost16);
    cudaGetSymbolAddress(&pool1,   d_pool1);
    cudaGetSymbolAddress(&m1,      d_m1);
    cudaGetSymbolAddress(&pool2,   d_pool2);
    cudaGetSymbolAddress(&m2,      d_m2);
    cudaGetSymbolAddress(&outis,   d_outis);
    cudaGetSymbolAddress(&s1a,     d_S1a);
    cudaGetSymbolAddress(&s2a,     d_S2a);
    cudaGetSymbolAddress(&s1b,     d_S1b);
    cudaGetSymbolAddress(&s2b,     d_S2b);

    const int CB = (NN * 32 + 255) / 256;  // 12500
    const int GB = (NN + 127) / 128;       // 782
    const int PB = GG * 8;                 // 800

    csr_kernel<<<GG, 512>>>(src, dst, ew);

    // ---- layer 1 ----
    gemm_kernel<64, true, false, false><<<GB, 256>>>(
        node_feats, W1, (const float*)outis, nullptr, (__half*)hpre16, nullptr);
    conv_kernel<<<CB, 256>>>((const __half*)hpre16, (__half*)conv16,
                             (float*)s1a, (float*)s2a);
    normB_kernel<<<GG * 4, 256>>>((const __half*)conv16, (const float*)s1a, (const float*)s2a,
                                  gn1a, gn1g, gn1b, (__half*)hpost16, (float*)m1);

    gemm_kernel<128, false, true, true><<<PB, 256>>>(
        hpost16, r1w1, nullptr, r1b1, nullptr, (float*)pool1);

    // ---- layer 2 ----
    gemm_kernel<128, true, false, true><<<GB, 256>>>(
        hpost16, W2, (const float*)outis, nullptr, (__half*)hpre16, nullptr);
    conv_kernel<<<CB, 256>>>((const __half*)hpre16, (__half*)conv16,
                             (float*)s1b, (float*)s2b);
    normB_kernel<<<GG * 4, 256>>>((const __half*)conv16, (const float*)s1b, (const float*)s2b,
                                  gn2a, gn2g, gn2b, (__half*)hpost16, (float*)m2);

    gemm_kernel<128, false, true, true><<<PB, 256>>>(
        hpost16, r2w1, nullptr, r2b1, nullptr, (float*)pool2);

    final_kernel<<<GG, 128>>>((const float*)pool1, (const float*)m1,
                              (const float*)pool2, (const float*)m2,
                              r1w2, r1b2, r2w2, r2b2, out);
}

// round 15
// speedup vs baseline: 1.1058x; 1.1058x over previous
#include <cuda_runtime.h>
#include <cuda_fp16.h>
#include <cstddef>

#define NN   100000
#define EE   1600000
#define GG   100
#define NPG  1000
#define EPG  16000
#define HH   128
#define FIN  64
#define RD   64
#define SLOPE 0.01f
#define EPSN  1e-5f

typedef unsigned long long u64;
typedef unsigned int u32;

__device__ __forceinline__ u64 pack2(float a, float b) {
    u64 r; asm("mov.b64 %0,{%1,%2};" : "=l"(r) : "f"(a), "f"(b)); return r;
}
__device__ __forceinline__ u64 ffma2(u64 a, u64 b, u64 c) {
    u64 d; asm("fma.rn.f32x2 %0,%1,%2,%3;" : "=l"(d) : "l"(a), "l"(b), "l"(c)); return d;
}
__device__ __forceinline__ float2 unpack2(u64 v) {
    float2 f; asm("mov.b64 {%0,%1},%2;" : "=f"(f.x), "=f"(f.y) : "l"(v)); return f;
}
__device__ __forceinline__ float leaky(float x) { return x >= 0.f ? x : SLOPE * x; }

// ---------------- scratch ----------------
__device__ int    d_rowstart[NN + 1];
__device__ int2   d_edge[EE];              // (src, __float_as_int(w))
__device__ float  d_outis[NN];
__device__ float  d_inis[NN];
__device__ __half d_hpre16[(size_t)NN * HH];
__device__ __half d_conv16[(size_t)NN * HH];
__device__ __half d_hpost16[(size_t)NN * HH];
__device__ float  d_pool1[GG * HH];
__device__ float  d_m1[GG * HH];
__device__ float  d_pool2[GG * HH];
__device__ float  d_m2[GG * HH];
__device__ float  d_S1a[GG * HH];
__device__ float  d_S2a[GG * HH];
__device__ float  d_S1b[GG * HH];
__device__ float  d_S2b[GG * HH];

// ---------------- fused per-graph CSR build + accumulator zeroing ----------------
__global__ __launch_bounds__(512)
void csr_kernel(const int* __restrict__ src, const int* __restrict__ dst,
                const float* __restrict__ ew) {
    __shared__ int cin[NPG], cout[NPG], cur[NPG], part[256];
    int g = blockIdx.x, t = threadIdx.x;
    int nbase = g * NPG;
    int e0 = g * EPG;

    if (t < 128) {
        int i = g * HH + t;
        d_pool1[i] = 0.f; d_pool2[i] = 0.f;
        d_m1[i] = 0.f;    d_m2[i] = 0.f;
        d_S1a[i] = 0.f;   d_S2a[i] = 0.f;
        d_S1b[i] = 0.f;   d_S2b[i] = 0.f;
    }
    for (int i = t; i < NPG; i += 512) { cin[i] = 0; cout[i] = 0; }
    __syncthreads();

    for (int e = t; e < EPG; e += 512) {
        atomicAdd(&cin[dst[e0 + e] - nbase], 1);
        atomicAdd(&cout[src[e0 + e] - nbase], 1);
    }
    __syncthreads();

    for (int i = t; i < NPG; i += 512) {
        int ci = cin[i];  if (ci < 1) ci = 1;
        int co = cout[i]; if (co < 1) co = 1;
        d_inis[nbase + i]  = rsqrtf((float)ci);
        d_outis[nbase + i] = rsqrtf((float)co);
    }

    int s = 0;
    if (t < 250) {
#pragma unroll
        for (int j = 0; j < 4; j++) s += cin[t * 4 + j];
    }
    if (t < 256) part[t] = s;
    __syncthreads();
    for (int o = 1; o < 256; o <<= 1) {
        int v = 0;
        if (t >= o && t < 256) v = part[t - o];
        __syncthreads();
        if (t < 256) part[t] += v;
        __syncthreads();
    }
    int run = (t == 0 || t >= 256) ? 0 : part[t - 1];
    if (t < 250) {
#pragma unroll
        for (int j = 0; j < 4; j++) {
            int i = t * 4 + j;
            int c = cin[i];
            cur[i] = run;
            d_rowstart[nbase + i] = e0 + run;
            run += c;
        }
    }
    if (g == 0 && t == 511) d_rowstart[NN] = EE;
    __syncthreads();

    for (int e = t; e < EPG; e += 512) {
        int sv = src[e0 + e];
        int d  = dst[e0 + e] - nbase;
        float wv = ew[e0 + e];
        int p = atomicAdd(&cur[d], 1);
        d_edge[e0 + p] = make_int2(sv, __float_as_int(wv));
    }
}

// ---------------- tiled GEMM, f32x2, CTA=128x128, thread=8x8 ----------------
// POOL=false: Y[r] = (RS? scale[r]:1) * X[r] @ W  -> fp16
// POOL=true : pool[g] += sum_r leaky(X[r]@W + bias)
// IN16: X is fp16 (converted during staging)
template <int K, bool RS, bool POOL, bool IN16>
__global__ __launch_bounds__(256)
void gemm_kernel(const void* __restrict__ Xv,
                 const float* __restrict__ W,          // K x 128 row-major
                 const float* __restrict__ rowscale,
                 const float* __restrict__ bias,
                 __half* __restrict__ Y,
                 float* __restrict__ pool) {
    __shared__ float Xs[32][128];
    __shared__ float Ws[32][128];
    __shared__ float psum[128];
    __shared__ float bsm[128];
    int tid = threadIdx.x;
    int tx = tid & 15;
    int ty = tid >> 4;

    int row0, g = 0, validrows = 128;
    if (POOL) {
        g = blockIdx.x >> 3;
        int chunk = blockIdx.x & 7;
        row0 = g * NPG + chunk * 128;
        validrows = NPG - chunk * 128; if (validrows > 128) validrows = 128;
        if (tid < 128) { psum[tid] = 0.f; bsm[tid] = bias[tid]; }
    } else {
        row0 = blockIdx.x * 128;
    }

    u64 acc[32];
#pragma unroll
    for (int i = 0; i < 32; i++) acc[i] = 0ull;

    for (int k0 = 0; k0 < K; k0 += 32) {
        __syncthreads();
#pragma unroll
        for (int i = 0; i < 4; i++) {
            int s = tid + i * 256;
            int row = s >> 3;
            int kq = s & 7;
            int grow = row0 + row;
            float4 v = make_float4(0.f, 0.f, 0.f, 0.f);
            if (grow < NN) {
                if (IN16) {
                    uint2 raw = *(const uint2*)((const __half*)Xv + (size_t)grow * K + k0 + kq * 4);
                    float2 a = __half22float2(*(__half2*)&raw.x);
                    float2 b = __half22float2(*(__half2*)&raw.y);
                    v = make_float4(a.x, a.y, b.x, b.y);
                } else {
                    v = *(const float4*)((const float*)Xv + (size_t)grow * K + k0 + kq * 4);
                }
                if (RS) {
                    float sc = rowscale[grow];
                    v.x *= sc; v.y *= sc; v.z *= sc; v.w *= sc;
                }
            }
            Xs[kq * 4 + 0][row] = v.x;
            Xs[kq * 4 + 1][row] = v.y;
            Xs[kq * 4 + 2][row] = v.z;
            Xs[kq * 4 + 3][row] = v.w;
        }
#pragma unroll
        for (int i = 0; i < 4; i++) {
            int s = tid + i * 256;
            int k = s >> 5;
            int cq = s & 31;
            *(float4*)&Ws[k][cq * 4] =
                *(const float4*)(W + (size_t)(k0 + k) * 128 + cq * 4);
        }
        __syncthreads();

#pragma unroll 8
        for (int kk = 0; kk < 32; kk++) {
            float xr[8];
            *(float4*)&xr[0] = *(const float4*)&Xs[kk][ty * 8];
            *(float4*)&xr[4] = *(const float4*)&Xs[kk][ty * 8 + 4];
            u64 x2[8];
#pragma unroll
            for (int r = 0; r < 8; r++) x2[r] = pack2(xr[r], xr[r]);
            const double2* wp = (const double2*)&Ws[kk][tx * 8];
            double2 wa = wp[0], wb = wp[1];
            u64 w2[4];
            w2[0] = __double_as_longlong(wa.x);
            w2[1] = __double_as_longlong(wa.y);
            w2[2] = __double_as_longlong(wb.x);
            w2[3] = __double_as_longlong(wb.y);
#pragma unroll
            for (int r = 0; r < 8; r++) {
#pragma unroll
                for (int c = 0; c < 4; c++)
                    acc[r * 4 + c] = ffma2(x2[r], w2[c], acc[r * 4 + c]);
            }
        }
    }

    if (!POOL) {
#pragma unroll
        for (int rr = 0; rr < 8; rr++) {
            int grow = row0 + ty * 8 + rr;
            if (grow < NN) {
                float2 p0 = unpack2(acc[rr * 4 + 0]);
                float2 p1 = unpack2(acc[rr * 4 + 1]);
                float2 p2 = unpack2(acc[rr * 4 + 2]);
                float2 p3 = unpack2(acc[rr * 4 + 3]);
                __half2 h0 = __floats2half2_rn(p0.x, p0.y);
                __half2 h1 = __floats2half2_rn(p1.x, p1.y);
                __half2 h2 = __floats2half2_rn(p2.x, p2.y);
                __half2 h3 = __floats2half2_rn(p3.x, p3.y);
                uint4 u;
                u.x = *(u32*)&h0; u.y = *(u32*)&h1;
                u.z = *(u32*)&h2; u.w = *(u32*)&h3;
                *(uint4*)(Y + (size_t)grow * 128 + tx * 8) = u;
            }
        }
    } else {
        float b[8];
#pragma unroll
        for (int j = 0; j < 8; j++) b[j] = bsm[tx * 8 + j];
        float cs[8];
#pragma unroll
        for (int j = 0; j < 8; j++) cs[j] = 0.f;
#pragma unroll
        for (int rr = 0; rr < 8; rr++) {
            if (ty * 8 + rr < validrows) {
#pragma unroll
                for (int c = 0; c < 4; c++) {
                    float2 p = unpack2(acc[rr * 4 + c]);
                    cs[2 * c]     += leaky(p.x + b[2 * c]);
                    cs[2 * c + 1] += leaky(p.y + b[2 * c + 1]);
                }
            }
        }
#pragma unroll
        for (int j = 0; j < 8; j++) atomicAdd(&psum[tx * 8 + j], cs[j]);
        __syncthreads();
        if (tid < 128) atomicAdd(&pool[g * 128 + tid], psum[tid]);
    }
}

// ---------------- edge aggregation (warp/node, shfl-broadcast edges, fp16 io) ----------------
__global__ __launch_bounds__(256)
void conv_kernel(const __half* __restrict__ hpre, __half* __restrict__ out) {
    int gt = blockIdx.x * blockDim.x + threadIdx.x;
    int node = gt >> 5;
    int lane = gt & 31;
    if (node >= NN) return;
    int e0 = d_rowstart[node];
    int e1 = d_rowstart[node + 1];
    const uint2* hp = (const uint2*)hpre;
    float4 acc = make_float4(0.f, 0.f, 0.f, 0.f);
    for (int base = e0; base < e1; base += 32) {
        int m = e1 - base; if (m > 32) m = 32;
        int sv = 0; float wv = 0.f;
        if (lane < m) {
            int2 p = d_edge[base + lane];
            sv = p.x;
            wv = __int_as_float(p.y);
        }
        for (int j = 0; j < m; j++) {
            int s   = __shfl_sync(0xFFFFFFFFu, sv, j);
            float w = __shfl_sync(0xFFFFFFFFu, wv, j);
            uint2 v = hp[(size_t)s * 32 + lane];
            float2 fa = __half22float2(*(__half2*)&v.x);
            float2 fb = __half22float2(*(__half2*)&v.y);
            acc.x += fa.x * w; acc.y += fa.y * w;
            acc.z += fb.x * w; acc.w += fb.y * w;
        }
    }
    float sc = d_inis[node];
    __half2 h0 = __floats2half2_rn(acc.x * sc, acc.y * sc);
    __half2 h1 = __floats2half2_rn(acc.z * sc, acc.w * sc);
    uint2 u; u.x = *(u32*)&h0; u.y = *(u32*)&h1;
    ((uint2*)out)[(size_t)node * 32 + lane] = u;
}

// ---------------- GraphNorm stats (4 CTAs/graph x 512 thr, 4 sub-groups) ----------------
__global__ __launch_bounds__(512)
void normA_kernel(const __half* __restrict__ Yin,
                  float* __restrict__ S1, float* __restrict__ S2) {
    int g = blockIdx.x >> 2;
    int q = blockIdx.x & 3;
    int f = threadIdx.x & 127;
    int sub = threadIdx.x >> 7;             // 0..3
    int start = (250 * sub) >> 2;           // 0,62,125,187
    int cnt   = ((250 * (sub + 1)) >> 2) - start;  // 62,63,62,63
    const __half* base = Yin + ((size_t)g * NPG + q * 250 + start) * HH + f;
    float s1 = 0.f, s2 = 0.f;
#pragma unroll 4
    for (int i = 0; i < cnt; i++) {
        float v = __half2float(base[(size_t)i * HH]);
        s1 += v;
        s2 += v * v;
    }
    __shared__ float sm1[512], sm2[512];
    sm1[threadIdx.x] = s1;
    sm2[threadIdx.x] = s2;
    __syncthreads();
    if (sub == 0) {
        atomicAdd(&S1[g * HH + f], sm1[f] + sm1[128 + f] + sm1[256 + f] + sm1[384 + f]);
        atomicAdd(&S2[g * HH + f], sm2[f] + sm2[128 + f] + sm2[256 + f] + sm2[384 + f]);
    }
}

// ---------------- GraphNorm apply + leaky + fused m-pool (fp16 in/out, 512 thr) ----------------
__global__ __launch_bounds__(512)
void normB_kernel(const __half* __restrict__ Yin,
                  const float* __restrict__ S1, const float* __restrict__ S2,
                  const float* __restrict__ alpha, const float* __restrict__ gamma_,
                  const float* __restrict__ beta, __half* __restrict__ Yout,
                  float* __restrict__ mout) {
    int g = blockIdx.x >> 2;
    int q = blockIdx.x & 3;
    int f = threadIdx.x & 127;
    int sub = threadIdx.x >> 7;
    int start = (250 * sub) >> 2;
    int cnt   = ((250 * (sub + 1)) >> 2) - start;
    float a = alpha[f], gm = gamma_[f], bt = beta[f];
    float mean = S1[g * HH + f] * (1.f / NPG);
    float var = S2[g * HH + f] * (1.f / NPG) - (2.f * a - a * a) * mean * mean;
    float inv = rsqrtf(var + EPSN);
    float am = a * mean;
    size_t off = ((size_t)g * NPG + q * 250 + start) * HH + f;
    const __half* base = Yin + off;
    __half* obase = Yout + off;
    float so = 0.f;
#pragma unroll 4
    for (int i = 0; i < cnt; i++) {
        float v = __half2float(base[(size_t)i * HH]);
        float o = leaky(gm * (v - am) * inv + bt);
        obase[(size_t)i * HH] = __float2half(o);
        so += o;
    }
    __shared__ float sm[512];
    sm[threadIdx.x] = so;
    __syncthreads();
    if (sub == 0)
        atomicAdd(&mout[g * HH + f], sm[f] + sm[128 + f] + sm[256 + f] + sm[384 + f]);
}

// ---------------- final readout assembly ----------------
__global__ __launch_bounds__(128)
void final_kernel(const float* __restrict__ p1, const float* __restrict__ m1,
                  const float* __restrict__ p2, const float* __restrict__ m2,
                  const float* __restrict__ r1w2, const float* __restrict__ r1b2,
                  const float* __restrict__ r2w2, const float* __restrict__ r2b2,
                  float* __restrict__ out) {
    int g = blockIdx.x;
    int t = threadIdx.x;
    const float inv = 1.f / NPG;
    if (t < RD) {
        float a1 = 0.f, a2 = 0.f;
        const float* pp1 = p1 + g * HH;
        const float* pp2 = p2 + g * HH;
#pragma unroll 4
        for (int f = 0; f < HH; f++) {
            a1 += pp1[f] * r1w2[f * RD + t];
            a2 += pp2[f] * r2w2[f * RD + t];
        }
        a1 = a1 * inv + r1b2[t];
        a2 = a2 * inv + r2b2[t];
        out[g * 384 + t]       = leaky(leaky(a1));
        out[g * 384 + 192 + t] = leaky(leaky(a2));
    }
    out[g * 384 + 64 + t]  = leaky(m1[g * HH + t] * inv);
    out[g * 384 + 256 + t] = leaky(m2[g * HH + t] * inv);
}

// ---------------- host launch ----------------
extern "C" void kernel_launch(void* const* d_in, const int* in_sizes, int n_in,
                              void* d_out, int out_size) {
    const float* node_feats = (const float*)d_in[0];
    const float* ew         = (const float*)d_in[1];
    const float* W1         = (const float*)d_in[2];
    const float* W2         = (const float*)d_in[3];
    const float* gn1a       = (const float*)d_in[4];
    const float* gn1g       = (const float*)d_in[5];
    const float* gn1b       = (const float*)d_in[6];
    const float* gn2a       = (const float*)d_in[7];
    const float* gn2g       = (const float*)d_in[8];
    const float* gn2b       = (const float*)d_in[9];
    const float* r1w1       = (const float*)d_in[10];
    const float* r1b1       = (const float*)d_in[11];
    const float* r1w2       = (const float*)d_in[12];
    const float* r1b2       = (const float*)d_in[13];
    const float* r2w1       = (const float*)d_in[14];
    const float* r2b1       = (const float*)d_in[15];
    const float* r2w2       = (const float*)d_in[16];
    const float* r2b2       = (const float*)d_in[17];
    const int*   src        = (const int*)d_in[18];
    const int*   dst        = (const int*)d_in[19];
    float* out = (float*)d_out;

    void *hpre16, *conv16, *hpost16, *pool1, *m1, *pool2, *m2, *outis;
    void *s1a, *s2a, *s1b, *s2b;
    cudaGetSymbolAddress(&hpre16,  d_hpre16);
    cudaGetSymbolAddress(&conv16,  d_conv16);
    cudaGetSymbolAddress(&hpost16, d_hpost16);
    cudaGetSymbolAddress(&pool1,   d_pool1);
    cudaGetSymbolAddress(&m1,      d_m1);
    cudaGetSymbolAddress(&pool2,   d_pool2);
    cudaGetSymbolAddress(&m2,      d_m2);
    cudaGetSymbolAddress(&outis,   d_outis);
    cudaGetSymbolAddress(&s1a,     d_S1a);
    cudaGetSymbolAddress(&s2a,     d_S2a);
    cudaGetSymbolAddress(&s1b,     d_S1b);
    cudaGetSymbolAddress(&s2b,     d_S2b);

    const int CB = (NN * 32 + 255) / 256;  // 12500
    const int GB = (NN + 127) / 128;       // 782
    const int PB = GG * 8;                 // 800

    csr_kernel<<<GG, 512>>>(src, dst, ew);

    // ---- layer 1 ----
    gemm_kernel<64, true, false, false><<<GB, 256>>>(
        node_feats, W1, (const float*)outis, nullptr, (__half*)hpre16, nullptr);
    conv_kernel<<<CB, 256>>>((const __half*)hpre16, (__half*)conv16);
    normA_kernel<<<GG * 4, 512>>>((const __half*)conv16, (float*)s1a, (float*)s2a);
    normB_kernel<<<GG * 4, 512>>>((const __half*)conv16, (const float*)s1a, (const float*)s2a,
                                  gn1a, gn1g, gn1b, (__half*)hpost16, (float*)m1);

    gemm_kernel<128, false, true, true><<<PB, 256>>>(
        hpost16, r1w1, nullptr, r1b1, nullptr, (float*)pool1);

    // ---- layer 2 ----
    gemm_kernel<128, true, false, true><<<GB, 256>>>(
        hpost16, W2, (const float*)outis, nullptr, (__half*)hpre16, nullptr);
    conv_kernel<<<CB, 256>>>((const __half*)hpre16, (__half*)conv16);
    normA_kernel<<<GG * 4, 512>>>((const __half*)conv16, (float*)s1b, (float*)s2b);
    normB_kernel<<<GG * 4, 512>>>((const __half*)conv16, (const float*)s1b, (const float*)s2b,
                                  gn2a, gn2g, gn2b, (__half*)hpost16, (float*)m2);

    gemm_kernel<128, false, true, true><<<PB, 256>>>(
        hpost16, r2w1, nullptr, r2b1, nullptr, (float*)pool2);

    final_kernel<<<GG, 128>>>((const float*)pool1, (const float*)m1,
                              (const float*)pool2, (const float*)m2,
                              r1w2, r1b2, r2w2, r2b2, out);
}